// round 9
// baseline (speedup 1.0000x reference)
#include <cuda_runtime.h>
#include <cuda_fp16.h>
#include <cstdint>

// ---------------------------------------------------------------------------
// Problem constants
// ---------------------------------------------------------------------------
#define N_TOK 8192
#define CH    1024
#define KC    9
#define KTOT  (CH * KC)          // 9216

// GEMM tiling
#define BM 128
#define BN 128
#define BK 64
#define NKT (KTOT / BK)          // 144 k-tiles (divisible by 3)
#define APLANE 16384             // 128 rows x 128B (SW128 swizzled)
#define STAGE (2 * APLANE)       // A, B = 32 KB
#define NSTAGE 3
#define SMEM_TOTAL 98304         // 96 KB -> 2 CTAs/SM (epilogue needs ~93 KB)

// fused-epilogue smem layout
#define EPI_SMF_FLOATS (32 * 132)        // 16896 B as floats
#define EPI_STG_OFF 17024                // staging base (16B aligned)
#define EPI_STG_STRIDE 304               // bytes per thread (16B mult, 288 used)

// ---------------------------------------------------------------------------
// Device scratch
// ---------------------------------------------------------------------------
__device__ __align__(16) __half g_F  [(size_t)N_TOK * KTOT];  // layer-1 A
__device__ __align__(16) __half g_F2 [(size_t)N_TOK * KTOT];  // layer-2 A
__device__ __align__(16) __half g_W1 [(size_t)CH * KTOT];
__device__ __align__(16) __half g_W2 [(size_t)CH * KTOT];

// ---------------------------------------------------------------------------
// PTX helpers (sm_80-baseline only)
// ---------------------------------------------------------------------------
__device__ __forceinline__ void cp16(uint32_t s, const void* g) {
    asm volatile("cp.async.cg.shared.global [%0], [%1], 16;" :: "r"(s), "l"(g));
}
__device__ __forceinline__ void cp_commit() {
    asm volatile("cp.async.commit_group;" ::: "memory");
}
template <int N> __device__ __forceinline__ void cp_wait() {
    asm volatile("cp.async.wait_group %0;" :: "n"(N) : "memory");
}
__device__ __forceinline__ void ldsm4(uint32_t* r, uint32_t a) {
    asm volatile("ldmatrix.sync.aligned.m8n8.x4.shared.b16 {%0,%1,%2,%3}, [%4];"
                 : "=r"(r[0]), "=r"(r[1]), "=r"(r[2]), "=r"(r[3]) : "r"(a));
}
__device__ __forceinline__ void mma16816(float* c, const uint32_t* a,
                                         const uint32_t* b) {
    asm volatile(
        "mma.sync.aligned.m16n8k16.row.col.f32.f16.f16.f32 "
        "{%0,%1,%2,%3}, {%4,%5,%6,%7}, {%8,%9}, {%0,%1,%2,%3};"
        : "+f"(c[0]), "+f"(c[1]), "+f"(c[2]), "+f"(c[3])
        : "r"(a[0]), "r"(a[1]), "r"(a[2]), "r"(a[3]), "r"(b[0]), "r"(b[1]));
}
// SW128 swizzle within a 16KB plane: row in [0,128), chunk in [0,8) (16B units)
__device__ __forceinline__ uint32_t sw128(uint32_t row, uint32_t chunk) {
    return row * 128u + ((chunk ^ (row & 7u)) << 4);
}

// Cox-de Boor cubic splines, exact reference arithmetic. b[0..7] outputs.
__device__ __forceinline__ void spline9(float x, float* b9) {
    const float lo_g = -0.2f;
    const float h    = (0.2f - (-0.2f)) / 5.0f;
    float t[12];
#pragma unroll
    for (int m = 0; m < 12; m++) t[m] = (float)(m - 3) * h + lo_g;
    float b[11];
#pragma unroll
    for (int j = 0; j < 11; j++) b[j] = (x >= t[j] && x < t[j + 1]) ? 1.0f : 0.0f;
#pragma unroll
    for (int k = 1; k <= 3; k++) {
#pragma unroll
        for (int j = 0; j < 11 - k; j++) {
            float invL = 1.0f / (t[j + k] - t[j]);
            float invR = 1.0f / (t[j + k + 1] - t[j + 1]);
            b[j] = (x - t[j]) * invL * b[j] + (t[j + k + 1] - x) * invR * b[j + 1];
        }
    }
#pragma unroll
    for (int k = 0; k < 8; k++) b9[k] = b[k];
    b9[8] = x;
}

// ---------------------------------------------------------------------------
// Weight pack (both layers in one launch): W[n][i*9+kk]
// ---------------------------------------------------------------------------
__global__ void pack_w_kernel(const float* __restrict__ base_w1,
                              const float* __restrict__ spline_w1,
                              const float* __restrict__ base_w2,
                              const float* __restrict__ spline_w2) {
    int which = blockIdx.y;
    const float* __restrict__ base_w   = which ? base_w2 : base_w1;
    const float* __restrict__ spline_w = which ? spline_w2 : spline_w1;
    __half* __restrict__ W = which ? g_W2 : g_W1;
    size_t idx = (size_t)blockIdx.x * blockDim.x + threadIdx.x;
    if (idx >= (size_t)CH * KTOT) return;
    int n = (int)(idx / KTOT);
    int k = (int)(idx - (size_t)n * KTOT);
    int i = k / KC;
    int kk = k - i * KC;
    float v = (kk < 8) ? spline_w[((size_t)n * CH + i) * 8 + kk]
                       : base_w[(size_t)n * CH + i];
    W[idx] = __float2half_rn(v);
}

// ---------------------------------------------------------------------------
// Basis for layer 1 (from input x), fp16 out to g_F
// ---------------------------------------------------------------------------
__global__ void basis_kernel(const float* __restrict__ X) {
    __shared__ __align__(16) __half sv[256 * 9];
    int n  = blockIdx.y;
    int i0 = blockIdx.x * 256;
    int tid = threadIdx.x;
    float x = X[(size_t)n * CH + i0 + tid];

    float b9[9];
    spline9(x, b9);
#pragma unroll
    for (int k = 0; k < 9; k++) sv[tid * 9 + k] = __float2half_rn(b9[k]);
    __syncthreads();

    size_t base = (size_t)n * KTOT + (size_t)i0 * KC;
    const float4* s4 = reinterpret_cast<const float4*>(sv);
    float4* d4 = reinterpret_cast<float4*>(&g_F[base]);
    for (int c = tid; c < 288; c += 256) d4[c] = s4[c];
}

// ---------------------------------------------------------------------------
// GEMM: C = F * W^T, fp16 HMMA, fp32 accum. CTA 128x128x64, 8 warps (2m x 4n),
// 3-stage cp.async, SW128. layer==0: epilogue computes basis-2 -> g_F2 (fp16).
// layer==1: epilogue writes fp32 output.
// ---------------------------------------------------------------------------
__device__ __forceinline__ void load_stage(
    uint32_t sbuf, int kt, int m0, int n0, int tid,
    const __half* __restrict__ A, const __half* __restrict__ B) {
#pragma unroll
    for (int j = 0; j < 4; j++) {
        int c = tid + j * 256;
        uint32_t row = (uint32_t)c >> 3, ch = (uint32_t)c & 7;
        uint32_t soff = sw128(row, ch);
        size_t gA = (size_t)(m0 + row) * KTOT + kt * BK + ch * 8;
        size_t gB = (size_t)(n0 + row) * KTOT + kt * BK + ch * 8;
        cp16(sbuf + soff,          A + gA);
        cp16(sbuf + APLANE + soff, B + gB);
    }
}

__global__ __launch_bounds__(256, 2) void kan_gemm_kernel(int layer,
                                                          float* __restrict__ Cout) {
    extern __shared__ char smem[];
    uint32_t sb;
    {
        uint64_t tmp;
        asm("cvta.to.shared.u64 %0, %1;" : "=l"(tmp) : "l"(smem));
        sb = (uint32_t)tmp;
    }
    const __half* __restrict__ A = layer ? g_F2 : g_F;
    const __half* __restrict__ B = layer ? g_W2 : g_W1;

    const int tid = threadIdx.x;
    const int lane = tid & 31;
    const int wid = tid >> 5;
    const int warp_m = wid & 1;        // 2 m-slots of 64
    const int warp_n = wid >> 1;       // 4 n-slots of 32
    const int m0 = blockIdx.y * BM;
    const int n0 = blockIdx.x * BN;

    float acc[4][4][4];
#pragma unroll
    for (int i = 0; i < 4; i++)
#pragma unroll
        for (int j = 0; j < 4; j++)
#pragma unroll
            for (int r = 0; r < 4; r++) acc[i][j][r] = 0.0f;

    // prologue: stages 0 and 1 (2 committed groups -> loop uses cp_wait<1>)
    load_stage(sb, 0, m0, n0, tid, A, B);
    cp_commit();
    load_stage(sb + STAGE, 1, m0, n0, tid, A, B);
    cp_commit();

    // per-lane ldmatrix row/chunk bases
    const uint32_t arow = warp_m * 64 + (lane & 15);          // + mf*16
    const uint32_t achk = (uint32_t)(lane >> 4);              // + ks*2
    const uint32_t brow = warp_n * 32 + ((lane >> 4) << 3) + (lane & 7); // + nfp*16
    const uint32_t bchk = (uint32_t)((lane >> 3) & 1);        // + ks*2

    for (int kt = 0; kt < NKT; kt += 3) {
#pragma unroll
        for (int s = 0; s < 3; s++) {
            const int k = kt + s;
            // pending = {k, k+1}; wait until <=1 -> stage k landed
            cp_wait<1>();
            __syncthreads();   // publish stage k; fences iter k-1 reads of
                               // buffer (k+2)%3

            const uint32_t pbuf = sb + ((s + 2) % 3) * STAGE;
            const int u = k + 2;
            if (u < NKT)
                load_stage(pbuf, u, m0, n0, tid, A, B);
            cp_commit();

            const uint32_t buf = sb + s * STAGE;
#pragma unroll
            for (int ks = 0; ks < 4; ks++) {
                uint32_t af[4][4], bf[4][2];
#pragma unroll
                for (int mf = 0; mf < 4; mf++)
                    ldsm4(af[mf], buf + sw128(arow + mf * 16, achk + ks * 2));
#pragma unroll
                for (int nfp = 0; nfp < 2; nfp++) {
                    uint32_t rb = buf + APLANE +
                                  sw128(brow + nfp * 16, bchk + ks * 2);
                    uint32_t r4[4];
                    ldsm4(r4, rb);
                    bf[nfp * 2][0] = r4[0]; bf[nfp * 2][1] = r4[1];
                    bf[nfp * 2 + 1][0] = r4[2]; bf[nfp * 2 + 1][1] = r4[3];
                }
#pragma unroll
                for (int mf = 0; mf < 4; mf++)
#pragma unroll
                    for (int nf = 0; nf < 4; nf++)
                        mma16816(acc[mf][nf], af[mf], bf[nf]);
            }
        }
    }

    if (layer) {
        // plain epilogue: fp32 out
#pragma unroll
        for (int mf = 0; mf < 4; mf++) {
            int row = m0 + warp_m * 64 + mf * 16 + (lane >> 2);
#pragma unroll
            for (int nf = 0; nf < 4; nf++) {
                int col = n0 + warp_n * 32 + nf * 8 + (lane & 3) * 2;
                float2* p0 = reinterpret_cast<float2*>(&Cout[(size_t)row * CH + col]);
                float2* p1 = reinterpret_cast<float2*>(&Cout[(size_t)(row + 8) * CH + col]);
                *p0 = make_float2(acc[mf][nf][0], acc[mf][nf][1]);
                *p1 = make_float2(acc[mf][nf][2], acc[mf][nf][3]);
            }
        }
        return;
    }

    // fused epilogue: basis-2 on x1 (fp32 acc) -> g_F2 fp16
    __syncthreads();                    // mainloop smem reads complete
    float* smf = reinterpret_cast<float*>(smem);          // 32 x 132 floats
    char*  stg = smem + EPI_STG_OFF;                      // per-thread 304B

#pragma unroll
    for (int c = 0; c < 4; c++) {
        // phase A: owning warps deposit 32 rows x 128 cols of x1 into smf
        if (warp_m == (c >> 1)) {
#pragma unroll
            for (int mf2 = 0; mf2 < 2; mf2++) {
                int mf = (c & 1) * 2 + mf2;
#pragma unroll
                for (int nf = 0; nf < 4; nf++)
#pragma unroll
                    for (int r = 0; r < 4; r++) {
                        int rl = mf2 * 16 + (lane >> 2) + (r >> 1) * 8;
                        int cl = warp_n * 32 + nf * 8 + (lane & 3) * 2 + (r & 1);
                        smf[rl * 132 + cl] = acc[mf][nf][r];
                    }
            }
        }
        __syncthreads();

        // phase B: all 256 threads convert 16 values each
        int rl = tid >> 3;
        int g  = (tid & 7) * 16;
        __half* hstg = reinterpret_cast<__half*>(stg + tid * EPI_STG_STRIDE);
#pragma unroll
        for (int i = 0; i < 16; i++) {
            float v = smf[rl * 132 + g + i];
            float b9[9];
            spline9(v, b9);
#pragma unroll
            for (int k = 0; k < 9; k++)
                hstg[i * 9 + k] = __float2half_rn(b9[k]);
        }
        // copy 288B staging -> global (coalesced 18 x float4)
        size_t drow = (size_t)(m0 + c * 32 + rl) * KTOT + (size_t)(n0 + g) * KC;
        float4* dst = reinterpret_cast<float4*>(g_F2 + drow);
        const float4* src = reinterpret_cast<const float4*>(stg + tid * EPI_STG_STRIDE);
#pragma unroll
        for (int w = 0; w < 18; w++) dst[w] = src[w];
        __syncthreads();                // smf reused next chunk
    }
}

// ---------------------------------------------------------------------------
// Launch: pack (1), basis1 (1), gemm1+fused basis2 (1), gemm2 (1)
// ---------------------------------------------------------------------------
extern "C" void kernel_launch(void* const* d_in, const int* in_sizes, int n_in,
                              void* d_out, int out_size) {
    (void)in_sizes; (void)n_in; (void)out_size;
    const float* x   = (const float*)d_in[0];
    const float* bw1 = (const float*)d_in[1];
    const float* sw1 = (const float*)d_in[2];
    const float* bw2 = (const float*)d_in[3];
    const float* sw2 = (const float*)d_in[4];
    float* out = (float*)d_out;

    cudaFuncSetAttribute(kan_gemm_kernel,
                         cudaFuncAttributeMaxDynamicSharedMemorySize, SMEM_TOTAL);

    dim3 packGrid((CH * KTOT + 255) / 256, 2);
    pack_w_kernel<<<packGrid, 256>>>(bw1, sw1, bw2, sw2);

    dim3 basGrid(CH / 256, N_TOK);
    basis_kernel<<<basGrid, 256>>>(x);

    dim3 gemmGrid(CH / BN, N_TOK / BM);   // (8, 64)
    kan_gemm_kernel<<<gemmGrid, 256, SMEM_TOTAL>>>(0, out);
    kan_gemm_kernel<<<gemmGrid, 256, SMEM_TOTAL>>>(1, out);
}

// round 10
// speedup vs baseline: 1.0943x; 1.0943x over previous
#include <cuda_runtime.h>
#include <cuda_fp16.h>
#include <cstdint>

// ---------------------------------------------------------------------------
// Problem constants
// ---------------------------------------------------------------------------
#define N_TOK 8192
#define CH    1024
#define KC    9
#define KTOT  (CH * KC)          // 9216

// GEMM tiling
#define BM 128
#define BN 128
#define BK 64
#define NKT (KTOT / BK)          // 144 k-tiles (divisible by 3)
#define APLANE 16384             // 128 rows x 128B (SW128 swizzled)
#define STAGE (2 * APLANE)       // A, B = 32 KB
#define SMEM_TOTAL 98304         // 3 stages = 96 KB -> 2 CTAs/SM

// ---------------------------------------------------------------------------
// Device scratch
// ---------------------------------------------------------------------------
__device__ __align__(16) __half g_F  [(size_t)N_TOK * KTOT];
__device__ __align__(16) __half g_W1 [(size_t)CH * KTOT];
__device__ __align__(16) __half g_W2 [(size_t)CH * KTOT];
__device__ __align__(16) float  g_X1 [(size_t)N_TOK * CH];

// ---------------------------------------------------------------------------
// PTX helpers (sm_80-baseline only)
// ---------------------------------------------------------------------------
__device__ __forceinline__ void cp16(uint32_t s, const void* g) {
    asm volatile("cp.async.cg.shared.global [%0], [%1], 16;" :: "r"(s), "l"(g));
}
__device__ __forceinline__ void cp_commit() {
    asm volatile("cp.async.commit_group;" ::: "memory");
}
template <int N> __device__ __forceinline__ void cp_wait() {
    asm volatile("cp.async.wait_group %0;" :: "n"(N) : "memory");
}
__device__ __forceinline__ void ldsm4(uint32_t* r, uint32_t a) {
    asm volatile("ldmatrix.sync.aligned.m8n8.x4.shared.b16 {%0,%1,%2,%3}, [%4];"
                 : "=r"(r[0]), "=r"(r[1]), "=r"(r[2]), "=r"(r[3]) : "r"(a));
}
__device__ __forceinline__ void mma16816(float* c, const uint32_t* a,
                                         const uint32_t* b) {
    asm volatile(
        "mma.sync.aligned.m16n8k16.row.col.f32.f16.f16.f32 "
        "{%0,%1,%2,%3}, {%4,%5,%6,%7}, {%8,%9}, {%0,%1,%2,%3};"
        : "+f"(c[0]), "+f"(c[1]), "+f"(c[2]), "+f"(c[3])
        : "r"(a[0]), "r"(a[1]), "r"(a[2]), "r"(a[3]), "r"(b[0]), "r"(b[1]));
}
// SW128 swizzle within a 16KB plane: row in [0,128), chunk in [0,8) (16B units)
__device__ __forceinline__ uint32_t sw128(uint32_t row, uint32_t chunk) {
    return row * 128u + ((chunk ^ (row & 7u)) << 4);
}

// Cox-de Boor cubic splines, exact reference arithmetic.
__device__ __forceinline__ void spline9(float x, float* b9) {
    const float lo_g = -0.2f;
    const float h    = (0.2f - (-0.2f)) / 5.0f;
    float t[12];
#pragma unroll
    for (int m = 0; m < 12; m++) t[m] = (float)(m - 3) * h + lo_g;
    float b[11];
#pragma unroll
    for (int j = 0; j < 11; j++) b[j] = (x >= t[j] && x < t[j + 1]) ? 1.0f : 0.0f;
#pragma unroll
    for (int k = 1; k <= 3; k++) {
#pragma unroll
        for (int j = 0; j < 11 - k; j++) {
            float invL = 1.0f / (t[j + k] - t[j]);
            float invR = 1.0f / (t[j + k + 1] - t[j + 1]);
            b[j] = (x - t[j]) * invL * b[j] + (t[j + k + 1] - x) * invR * b[j + 1];
        }
    }
#pragma unroll
    for (int k = 0; k < 8; k++) b9[k] = b[k];
    b9[8] = x;
}

// ---------------------------------------------------------------------------
// Weight pack (both layers, one launch): W[n][i*9+kk]
// ---------------------------------------------------------------------------
__global__ void pack_w_kernel(const float* __restrict__ base_w1,
                              const float* __restrict__ spline_w1,
                              const float* __restrict__ base_w2,
                              const float* __restrict__ spline_w2) {
    int which = blockIdx.y;
    const float* __restrict__ base_w   = which ? base_w2 : base_w1;
    const float* __restrict__ spline_w = which ? spline_w2 : spline_w1;
    __half* __restrict__ W = which ? g_W2 : g_W1;
    size_t idx = (size_t)blockIdx.x * blockDim.x + threadIdx.x;
    if (idx >= (size_t)CH * KTOT) return;
    int n = (int)(idx / KTOT);
    int k = (int)(idx - (size_t)n * KTOT);
    int i = k / KC;
    int kk = k - i * KC;
    float v = (kk < 8) ? spline_w[((size_t)n * CH + i) * 8 + kk]
                       : base_w[(size_t)n * CH + i];
    W[idx] = __float2half_rn(v);
}

// ---------------------------------------------------------------------------
// Basis: one token row per block. 256 threads, thread t handles i = 4t..4t+3.
// Full 1024x9 fp16 row staged in smem, then 1152 coalesced float4 stores.
// ---------------------------------------------------------------------------
__global__ __launch_bounds__(256) void basis_kernel(const float* __restrict__ Xext,
                                                    int use_x1) {
    const float* __restrict__ X = use_x1 ? g_X1 : Xext;
    __shared__ __align__(16) __half sv[CH * KC];   // 18432 B

    int n = blockIdx.x;
    int t = threadIdx.x;
    float4 x4 = reinterpret_cast<const float4*>(X + (size_t)n * CH)[t];
    float xs[4] = {x4.x, x4.y, x4.z, x4.w};

#pragma unroll
    for (int j = 0; j < 4; j++) {
        float b9[9];
        spline9(xs[j], b9);
#pragma unroll
        for (int k = 0; k < 9; k++)
            sv[t * 36 + j * 9 + k] = __float2half_rn(b9[k]);
    }
    __syncthreads();

    const float4* s4 = reinterpret_cast<const float4*>(sv);
    float4* d4 = reinterpret_cast<float4*>(&g_F[(size_t)n * KTOT]);
#pragma unroll
    for (int c = t; c < 1152; c += 256) d4[c] = s4[c];
}

// ---------------------------------------------------------------------------
// GEMM: C = F * W^T, fp16 HMMA, fp32 accum. CTA 128x128x64, 8 warps (2m x 4n),
// 3-stage cp.async, SW128, one barrier per k-tile.
// ---------------------------------------------------------------------------
__device__ __forceinline__ void load_stage(
    uint32_t sbuf, int kt, int m0, int n0, int tid,
    const __half* __restrict__ A, const __half* __restrict__ B) {
#pragma unroll
    for (int j = 0; j < 4; j++) {
        int c = tid + j * 256;
        uint32_t row = (uint32_t)c >> 3, ch = (uint32_t)c & 7;
        uint32_t soff = sw128(row, ch);
        size_t gA = (size_t)(m0 + row) * KTOT + kt * BK + ch * 8;
        size_t gB = (size_t)(n0 + row) * KTOT + kt * BK + ch * 8;
        cp16(sbuf + soff,          A + gA);
        cp16(sbuf + APLANE + soff, B + gB);
    }
}

__global__ __launch_bounds__(256, 2) void kan_gemm_kernel(int layer,
                                                          float* __restrict__ Cout) {
    extern __shared__ char smem[];
    uint32_t sb;
    {
        uint64_t tmp;
        asm("cvta.to.shared.u64 %0, %1;" : "=l"(tmp) : "l"(smem));
        sb = (uint32_t)tmp;
    }
    const __half* __restrict__ A = g_F;
    const __half* __restrict__ B = layer ? g_W2 : g_W1;
    float* __restrict__ C = layer ? Cout : g_X1;

    const int tid = threadIdx.x;
    const int lane = tid & 31;
    const int wid = tid >> 5;
    const int warp_m = wid & 1;        // 2 m-slots of 64
    const int warp_n = wid >> 1;       // 4 n-slots of 32
    const int m0 = blockIdx.y * BM;
    const int n0 = blockIdx.x * BN;

    float acc[4][4][4];
#pragma unroll
    for (int i = 0; i < 4; i++)
#pragma unroll
        for (int j = 0; j < 4; j++)
#pragma unroll
            for (int r = 0; r < 4; r++) acc[i][j][r] = 0.0f;

    // prologue: stages 0 and 1 (2 committed groups -> loop uses cp_wait<1>)
    load_stage(sb, 0, m0, n0, tid, A, B);
    cp_commit();
    load_stage(sb + STAGE, 1, m0, n0, tid, A, B);
    cp_commit();

    // per-lane ldmatrix row/chunk bases
    const uint32_t arow = warp_m * 64 + (lane & 15);          // + mf*16
    const uint32_t achk = (uint32_t)(lane >> 4);              // + ks*2
    const uint32_t brow = warp_n * 32 + ((lane >> 4) << 3) + (lane & 7); // + nfp*16
    const uint32_t bchk = (uint32_t)((lane >> 3) & 1);        // + ks*2

    for (int kt = 0; kt < NKT; kt += 3) {
#pragma unroll
        for (int s = 0; s < 3; s++) {
            const int k = kt + s;
            // pending = {k, k+1}; wait until <=1 -> stage k landed
            cp_wait<1>();
            __syncthreads();   // publish stage k; fences iter k-1 reads of
                               // buffer (k+2)%3

            const uint32_t pbuf = sb + ((s + 2) % 3) * STAGE;
            const int u = k + 2;
            if (u < NKT)
                load_stage(pbuf, u, m0, n0, tid, A, B);
            cp_commit();

            const uint32_t buf = sb + s * STAGE;
#pragma unroll
            for (int ks = 0; ks < 4; ks++) {
                uint32_t af[4][4], bf[4][2];
#pragma unroll
                for (int mf = 0; mf < 4; mf++)
                    ldsm4(af[mf], buf + sw128(arow + mf * 16, achk + ks * 2));
#pragma unroll
                for (int nfp = 0; nfp < 2; nfp++) {
                    uint32_t rb = buf + APLANE +
                                  sw128(brow + nfp * 16, bchk + ks * 2);
                    uint32_t r4[4];
                    ldsm4(r4, rb);
                    bf[nfp * 2][0] = r4[0]; bf[nfp * 2][1] = r4[1];
                    bf[nfp * 2 + 1][0] = r4[2]; bf[nfp * 2 + 1][1] = r4[3];
                }
#pragma unroll
                for (int mf = 0; mf < 4; mf++)
#pragma unroll
                    for (int nf = 0; nf < 4; nf++)
                        mma16816(acc[mf][nf], af[mf], bf[nf]);
            }
        }
    }

    // plain epilogue: fp32 out (g_X1 for layer 0, harness out for layer 1)
#pragma unroll
    for (int mf = 0; mf < 4; mf++) {
        int row = m0 + warp_m * 64 + mf * 16 + (lane >> 2);
#pragma unroll
        for (int nf = 0; nf < 4; nf++) {
            int col = n0 + warp_n * 32 + nf * 8 + (lane & 3) * 2;
            float2* p0 = reinterpret_cast<float2*>(&C[(size_t)row * CH + col]);
            float2* p1 = reinterpret_cast<float2*>(&C[(size_t)(row + 8) * CH + col]);
            *p0 = make_float2(acc[mf][nf][0], acc[mf][nf][1]);
            *p1 = make_float2(acc[mf][nf][2], acc[mf][nf][3]);
        }
    }
}

// ---------------------------------------------------------------------------
// Launch: pack (1) -> basis1 -> gemm1 -> basis2 -> gemm2
// ---------------------------------------------------------------------------
extern "C" void kernel_launch(void* const* d_in, const int* in_sizes, int n_in,
                              void* d_out, int out_size) {
    (void)in_sizes; (void)n_in; (void)out_size;
    const float* x   = (const float*)d_in[0];
    const float* bw1 = (const float*)d_in[1];
    const float* sw1 = (const float*)d_in[2];
    const float* bw2 = (const float*)d_in[3];
    const float* sw2 = (const float*)d_in[4];
    float* out = (float*)d_out;

    cudaFuncSetAttribute(kan_gemm_kernel,
                         cudaFuncAttributeMaxDynamicSharedMemorySize, SMEM_TOTAL);

    dim3 packGrid((CH * KTOT + 255) / 256, 2);
    pack_w_kernel<<<packGrid, 256>>>(bw1, sw1, bw2, sw2);

    dim3 gemmGrid(CH / BN, N_TOK / BM);   // (8, 64)

    basis_kernel<<<N_TOK, 256>>>(x, 0);
    kan_gemm_kernel<<<gemmGrid, 256, SMEM_TOTAL>>>(0, out);
    basis_kernel<<<N_TOK, 256>>>(x, 1);
    kan_gemm_kernel<<<gemmGrid, 256, SMEM_TOTAL>>>(1, out);
}

// round 11
// speedup vs baseline: 1.1953x; 1.0923x over previous
#include <cuda_runtime.h>
#include <cuda_fp16.h>
#include <cstdint>

// ---------------------------------------------------------------------------
// Problem constants
// ---------------------------------------------------------------------------
#define N_TOK 8192
#define CH    1024
#define KC    9
#define KTOT  (CH * KC)          // 9216

// GEMM tiling
#define BM 128
#define BN 128
#define BK 64
#define NKT (KTOT / BK)          // 144 k-tiles (divisible by 3)
#define APLANE 16384             // 128 rows x 128B (SW128 swizzled)
#define STAGE (2 * APLANE)       // A, B = 32 KB
#define SMEM_TOTAL 98304         // 3 stages = 96 KB -> 2 CTAs/SM

// ---------------------------------------------------------------------------
// Device scratch
// ---------------------------------------------------------------------------
__device__ __align__(16) __half g_F  [(size_t)N_TOK * KTOT];
__device__ __align__(16) __half g_W1 [(size_t)CH * KTOT];
__device__ __align__(16) __half g_W2 [(size_t)CH * KTOT];
__device__ __align__(16) float  g_X1 [(size_t)N_TOK * CH];

// ---------------------------------------------------------------------------
// PTX helpers (sm_80-baseline only)
// ---------------------------------------------------------------------------
__device__ __forceinline__ void cp16(uint32_t s, const void* g) {
    asm volatile("cp.async.cg.shared.global [%0], [%1], 16;" :: "r"(s), "l"(g));
}
__device__ __forceinline__ void cp_commit() {
    asm volatile("cp.async.commit_group;" ::: "memory");
}
template <int N> __device__ __forceinline__ void cp_wait() {
    asm volatile("cp.async.wait_group %0;" :: "n"(N) : "memory");
}
__device__ __forceinline__ void ldsm4(uint32_t* r, uint32_t a) {
    asm volatile("ldmatrix.sync.aligned.m8n8.x4.shared.b16 {%0,%1,%2,%3}, [%4];"
                 : "=r"(r[0]), "=r"(r[1]), "=r"(r[2]), "=r"(r[3]) : "r"(a));
}
__device__ __forceinline__ void mma16816(float* c, const uint32_t* a,
                                         const uint32_t* b) {
    asm volatile(
        "mma.sync.aligned.m16n8k16.row.col.f32.f16.f16.f32 "
        "{%0,%1,%2,%3}, {%4,%5,%6,%7}, {%8,%9}, {%0,%1,%2,%3};"
        : "+f"(c[0]), "+f"(c[1]), "+f"(c[2]), "+f"(c[3])
        : "r"(a[0]), "r"(a[1]), "r"(a[2]), "r"(a[3]), "r"(b[0]), "r"(b[1]));
}
// SW128 swizzle within a 16KB plane: row in [0,128), chunk in [0,8) (16B units)
__device__ __forceinline__ uint32_t sw128(uint32_t row, uint32_t chunk) {
    return row * 128u + ((chunk ^ (row & 7u)) << 4);
}

// ---------------------------------------------------------------------------
// Closed-form uniform cubic B-spline: only 4 bases nonzero. Knots
// t_m = 0.08*m - 0.44, m=0..11. For x in [t_m, t_{m+1}): nonzero bases are
// j = m-3..m (clipped to [0,8)) with the standard uniform segment polynomials.
// Outside [t_0, t_11): all zero (matches the reference's empty indicator).
// ---------------------------------------------------------------------------
__device__ __forceinline__ void spline9(float x, float* b9) {
#pragma unroll
    for (int k = 0; k < 8; k++) b9[k] = 0.0f;
    b9[8] = x;
    float s = (x + 0.44f) * 12.5f;        // (x - t0)/h
    int m = (int)floorf(s);
    if (m < 0 || m > 10) return;
    float u  = s - (float)m;              // local coordinate in [0,1)
    float v  = 1.0f - u;
    float u2 = u * u, u3 = u2 * u;
    const float c6 = 1.0f / 6.0f;
    float nv[4];
    nv[0] = v * v * v * c6;                               // b_{m-3}
    nv[1] = (3.0f * u3 - 6.0f * u2 + 4.0f) * c6;          // b_{m-2}
    nv[2] = (-3.0f * u3 + 3.0f * u2 + 3.0f * u + 1.0f) * c6; // b_{m-1}
    nv[3] = u3 * c6;                                      // b_m
#pragma unroll
    for (int i = 0; i < 4; i++) {
        int j = m - 3 + i;
        if (j >= 0 && j < 8) b9[j] = nv[i];
    }
}

// ---------------------------------------------------------------------------
// Weight pack: one block per output row n (grid.y = layer). Contiguous reads
// (spline_w row = 8192 floats) and contiguous writes via smem staging.
// ---------------------------------------------------------------------------
__global__ __launch_bounds__(256) void pack_w_kernel(
    const float* __restrict__ base_w1, const float* __restrict__ spline_w1,
    const float* __restrict__ base_w2, const float* __restrict__ spline_w2) {
    int which = blockIdx.y;
    int n = blockIdx.x;
    const float* __restrict__ bw = which ? base_w2 : base_w1;
    const float* __restrict__ sp = which ? spline_w2 : spline_w1;
    __half* __restrict__ W = which ? g_W2 : g_W1;

    __shared__ __align__(16) __half sv[KTOT];   // 18432 B
    int t = threadIdx.x;
#pragma unroll
    for (int j = 0; j < 4; j++) {
        int i = t + j * 256;
        const float4* s4 = reinterpret_cast<const float4*>(
            sp + ((size_t)n * CH + i) * 8);
        float4 a = s4[0], b = s4[1];
        float base = bw[(size_t)n * CH + i];
        __half* dst = &sv[i * 9];
        dst[0] = __float2half_rn(a.x); dst[1] = __float2half_rn(a.y);
        dst[2] = __float2half_rn(a.z); dst[3] = __float2half_rn(a.w);
        dst[4] = __float2half_rn(b.x); dst[5] = __float2half_rn(b.y);
        dst[6] = __float2half_rn(b.z); dst[7] = __float2half_rn(b.w);
        dst[8] = __float2half_rn(base);
    }
    __syncthreads();
    const float4* s4 = reinterpret_cast<const float4*>(sv);
    float4* d4 = reinterpret_cast<float4*>(W + (size_t)n * KTOT);
#pragma unroll
    for (int c = t; c < 1152; c += 256) d4[c] = s4[c];
}

// ---------------------------------------------------------------------------
// Basis: one token row per block, closed-form splines, smem-staged stores.
// ---------------------------------------------------------------------------
__global__ __launch_bounds__(256) void basis_kernel(const float* __restrict__ Xext,
                                                    int use_x1) {
    const float* __restrict__ X = use_x1 ? g_X1 : Xext;
    __shared__ __align__(16) __half sv[KTOT];   // 18432 B

    int n = blockIdx.x;
    int t = threadIdx.x;
    float4 x4 = reinterpret_cast<const float4*>(X + (size_t)n * CH)[t];
    float xs[4] = {x4.x, x4.y, x4.z, x4.w};

#pragma unroll
    for (int j = 0; j < 4; j++) {
        float b9[9];
        spline9(xs[j], b9);
#pragma unroll
        for (int k = 0; k < 9; k++)
            sv[t * 36 + j * 9 + k] = __float2half_rn(b9[k]);
    }
    __syncthreads();

    const float4* s4 = reinterpret_cast<const float4*>(sv);
    float4* d4 = reinterpret_cast<float4*>(&g_F[(size_t)n * KTOT]);
#pragma unroll
    for (int c = t; c < 1152; c += 256) d4[c] = s4[c];
}

// ---------------------------------------------------------------------------
// GEMM: C = F * W^T, fp16 HMMA, fp32 accum. CTA 128x128x64, 8 warps (2m x 4n),
// 3-stage cp.async, SW128, one barrier per k-tile.
// ---------------------------------------------------------------------------
__device__ __forceinline__ void load_stage(
    uint32_t sbuf, int kt, int m0, int n0, int tid,
    const __half* __restrict__ A, const __half* __restrict__ B) {
#pragma unroll
    for (int j = 0; j < 4; j++) {
        int c = tid + j * 256;
        uint32_t row = (uint32_t)c >> 3, ch = (uint32_t)c & 7;
        uint32_t soff = sw128(row, ch);
        size_t gA = (size_t)(m0 + row) * KTOT + kt * BK + ch * 8;
        size_t gB = (size_t)(n0 + row) * KTOT + kt * BK + ch * 8;
        cp16(sbuf + soff,          A + gA);
        cp16(sbuf + APLANE + soff, B + gB);
    }
}

__global__ __launch_bounds__(256, 2) void kan_gemm_kernel(int layer,
                                                          float* __restrict__ Cout) {
    extern __shared__ char smem[];
    uint32_t sb;
    {
        uint64_t tmp;
        asm("cvta.to.shared.u64 %0, %1;" : "=l"(tmp) : "l"(smem));
        sb = (uint32_t)tmp;
    }
    const __half* __restrict__ A = g_F;
    const __half* __restrict__ B = layer ? g_W2 : g_W1;
    float* __restrict__ C = layer ? Cout : g_X1;

    const int tid = threadIdx.x;
    const int lane = tid & 31;
    const int wid = tid >> 5;
    const int warp_m = wid & 1;        // 2 m-slots of 64
    const int warp_n = wid >> 1;       // 4 n-slots of 32
    const int m0 = blockIdx.y * BM;
    const int n0 = blockIdx.x * BN;

    float acc[4][4][4];
#pragma unroll
    for (int i = 0; i < 4; i++)
#pragma unroll
        for (int j = 0; j < 4; j++)
#pragma unroll
            for (int r = 0; r < 4; r++) acc[i][j][r] = 0.0f;

    // prologue: stages 0 and 1 (2 committed groups -> loop uses cp_wait<1>)
    load_stage(sb, 0, m0, n0, tid, A, B);
    cp_commit();
    load_stage(sb + STAGE, 1, m0, n0, tid, A, B);
    cp_commit();

    // per-lane ldmatrix row/chunk bases
    const uint32_t arow = warp_m * 64 + (lane & 15);          // + mf*16
    const uint32_t achk = (uint32_t)(lane >> 4);              // + ks*2
    const uint32_t brow = warp_n * 32 + ((lane >> 4) << 3) + (lane & 7); // + nfp*16
    const uint32_t bchk = (uint32_t)((lane >> 3) & 1);        // + ks*2

    for (int kt = 0; kt < NKT; kt += 3) {
#pragma unroll
        for (int s = 0; s < 3; s++) {
            const int k = kt + s;
            // pending = {k, k+1}; wait until <=1 -> stage k landed
            cp_wait<1>();
            __syncthreads();   // publish stage k; fences iter k-1 reads of
                               // buffer (k+2)%3

            const uint32_t pbuf = sb + ((s + 2) % 3) * STAGE;
            const int u = k + 2;
            if (u < NKT)
                load_stage(pbuf, u, m0, n0, tid, A, B);
            cp_commit();

            const uint32_t buf = sb + s * STAGE;
#pragma unroll
            for (int ks = 0; ks < 4; ks++) {
                uint32_t af[4][4], bf[4][2];
#pragma unroll
                for (int mf = 0; mf < 4; mf++)
                    ldsm4(af[mf], buf + sw128(arow + mf * 16, achk + ks * 2));
#pragma unroll
                for (int nfp = 0; nfp < 2; nfp++) {
                    uint32_t rb = buf + APLANE +
                                  sw128(brow + nfp * 16, bchk + ks * 2);
                    uint32_t r4[4];
                    ldsm4(r4, rb);
                    bf[nfp * 2][0] = r4[0]; bf[nfp * 2][1] = r4[1];
                    bf[nfp * 2 + 1][0] = r4[2]; bf[nfp * 2 + 1][1] = r4[3];
                }
#pragma unroll
                for (int mf = 0; mf < 4; mf++)
#pragma unroll
                    for (int nf = 0; nf < 4; nf++)
                        mma16816(acc[mf][nf], af[mf], bf[nf]);
            }
        }
    }

    // epilogue: fp32 out (g_X1 for layer 0, harness out for layer 1)
#pragma unroll
    for (int mf = 0; mf < 4; mf++) {
        int row = m0 + warp_m * 64 + mf * 16 + (lane >> 2);
#pragma unroll
        for (int nf = 0; nf < 4; nf++) {
            int col = n0 + warp_n * 32 + nf * 8 + (lane & 3) * 2;
            float2* p0 = reinterpret_cast<float2*>(&C[(size_t)row * CH + col]);
            float2* p1 = reinterpret_cast<float2*>(&C[(size_t)(row + 8) * CH + col]);
            *p0 = make_float2(acc[mf][nf][0], acc[mf][nf][1]);
            *p1 = make_float2(acc[mf][nf][2], acc[mf][nf][3]);
        }
    }
}

// ---------------------------------------------------------------------------
// Launch: pack -> basis1 -> gemm1 -> basis2 -> gemm2
// ---------------------------------------------------------------------------
extern "C" void kernel_launch(void* const* d_in, const int* in_sizes, int n_in,
                              void* d_out, int out_size) {
    (void)in_sizes; (void)n_in; (void)out_size;
    const float* x   = (const float*)d_in[0];
    const float* bw1 = (const float*)d_in[1];
    const float* sw1 = (const float*)d_in[2];
    const float* bw2 = (const float*)d_in[3];
    const float* sw2 = (const float*)d_in[4];
    float* out = (float*)d_out;

    cudaFuncSetAttribute(kan_gemm_kernel,
                         cudaFuncAttributeMaxDynamicSharedMemorySize, SMEM_TOTAL);

    dim3 packGrid(CH, 2);
    pack_w_kernel<<<packGrid, 256>>>(bw1, sw1, bw2, sw2);

    dim3 gemmGrid(CH / BN, N_TOK / BM);   // (8, 64)

    basis_kernel<<<N_TOK, 256>>>(x, 0);
    kan_gemm_kernel<<<gemmGrid, 256, SMEM_TOTAL>>>(0, out);
    basis_kernel<<<N_TOK, 256>>>(x, 1);
    kan_gemm_kernel<<<gemmGrid, 256, SMEM_TOTAL>>>(1, out);
}

// round 12
// speedup vs baseline: 1.2073x; 1.0101x over previous
#include <cuda_runtime.h>
#include <cuda_fp16.h>
#include <cstdint>

// ---------------------------------------------------------------------------
// Problem constants
// ---------------------------------------------------------------------------
#define N_TOK 8192
#define CH    1024
#define KC    9
#define KTOT  (CH * KC)          // 9216

// GEMM tiling
#define BM 128
#define BN 128
#define BK 64
#define NKT (KTOT / BK)          // 144 k-tiles (divisible by 3)
#define APLANE 16384             // 128 rows x 128B (SW128 swizzled)
#define STAGE (2 * APLANE)       // A, B = 32 KB
#define SMEM_TOTAL 98304         // 3 stages = 96 KB -> 2 CTAs/SM

// ---------------------------------------------------------------------------
// Device scratch
// ---------------------------------------------------------------------------
__device__ __align__(16) __half g_F  [(size_t)N_TOK * KTOT];
__device__ __align__(16) __half g_W1 [(size_t)CH * KTOT];
__device__ __align__(16) __half g_W2 [(size_t)CH * KTOT];
__device__ __align__(16) float  g_X1 [(size_t)N_TOK * CH];

// ---------------------------------------------------------------------------
// PTX helpers (sm_80-baseline only)
// ---------------------------------------------------------------------------
__device__ __forceinline__ void cp16(uint32_t s, const void* g) {
    asm volatile("cp.async.cg.shared.global [%0], [%1], 16;" :: "r"(s), "l"(g));
}
__device__ __forceinline__ void cp_commit() {
    asm volatile("cp.async.commit_group;" ::: "memory");
}
template <int N> __device__ __forceinline__ void cp_wait() {
    asm volatile("cp.async.wait_group %0;" :: "n"(N) : "memory");
}
__device__ __forceinline__ void ldsm4(uint32_t* r, uint32_t a) {
    asm volatile("ldmatrix.sync.aligned.m8n8.x4.shared.b16 {%0,%1,%2,%3}, [%4];"
                 : "=r"(r[0]), "=r"(r[1]), "=r"(r[2]), "=r"(r[3]) : "r"(a));
}
__device__ __forceinline__ void mma16816(float* c, const uint32_t* a,
                                         const uint32_t* b) {
    asm volatile(
        "mma.sync.aligned.m16n8k16.row.col.f32.f16.f16.f32 "
        "{%0,%1,%2,%3}, {%4,%5,%6,%7}, {%8,%9}, {%0,%1,%2,%3};"
        : "+f"(c[0]), "+f"(c[1]), "+f"(c[2]), "+f"(c[3])
        : "r"(a[0]), "r"(a[1]), "r"(a[2]), "r"(a[3]), "r"(b[0]), "r"(b[1]));
}
// SW128 swizzle within a 16KB plane: row in [0,128), chunk in [0,8) (16B units)
__device__ __forceinline__ uint32_t sw128(uint32_t row, uint32_t chunk) {
    return row * 128u + ((chunk ^ (row & 7u)) << 4);
}

// ---------------------------------------------------------------------------
// Weight pack: one block per output row n (grid.y = layer). Contiguous reads
// and contiguous writes via smem staging.
// ---------------------------------------------------------------------------
__global__ __launch_bounds__(256) void pack_w_kernel(
    const float* __restrict__ base_w1, const float* __restrict__ spline_w1,
    const float* __restrict__ base_w2, const float* __restrict__ spline_w2) {
    int which = blockIdx.y;
    int n = blockIdx.x;
    const float* __restrict__ bw = which ? base_w2 : base_w1;
    const float* __restrict__ sp = which ? spline_w2 : spline_w1;
    __half* __restrict__ W = which ? g_W2 : g_W1;

    __shared__ __align__(16) __half sv[KTOT];   // 18432 B
    int t = threadIdx.x;
#pragma unroll
    for (int j = 0; j < 4; j++) {
        int i = t + j * 256;
        const float4* s4 = reinterpret_cast<const float4*>(
            sp + ((size_t)n * CH + i) * 8);
        float4 a = s4[0], b = s4[1];
        float base = bw[(size_t)n * CH + i];
        __half* dst = &sv[i * 9];
        dst[0] = __float2half_rn(a.x); dst[1] = __float2half_rn(a.y);
        dst[2] = __float2half_rn(a.z); dst[3] = __float2half_rn(a.w);
        dst[4] = __float2half_rn(b.x); dst[5] = __float2half_rn(b.y);
        dst[6] = __float2half_rn(b.z); dst[7] = __float2half_rn(b.w);
        dst[8] = __float2half_rn(base);
    }
    __syncthreads();
    const float4* s4 = reinterpret_cast<const float4*>(sv);
    float4* d4 = reinterpret_cast<float4*>(W + (size_t)n * KTOT);
#pragma unroll
    for (int c = t; c < 1152; c += 256) d4[c] = s4[c];
}

// ---------------------------------------------------------------------------
// Basis: one token row per block, closed-form uniform cubic B-spline.
// Only 4 bases are nonzero: zero own smem block (9 x STS.64), then scatter
// 4 predicated STS.16 (+1 for the identity channel). Same arithmetic and
// selection as the previous select-chain version -> identical output.
// Knots t_m = 0.08*m - 0.44; x in [t_m, t_{m+1}) activates j = m-3..m.
// Outside [t_0, t_11): all zero (matches the reference's empty indicator).
// ---------------------------------------------------------------------------
__global__ __launch_bounds__(256) void basis_kernel(const float* __restrict__ Xext,
                                                    int use_x1) {
    const float* __restrict__ X = use_x1 ? g_X1 : Xext;
    __shared__ __align__(16) __half sv[KTOT];   // 18432 B

    int n = blockIdx.x;
    int t = threadIdx.x;
    float4 x4 = reinterpret_cast<const float4*>(X + (size_t)n * CH)[t];
    float xs[4] = {x4.x, x4.y, x4.z, x4.w};

    // zero own 36-half block (72 B, 8B-aligned at t*72)
    {
        uint64_t* z8 = reinterpret_cast<uint64_t*>(&sv[t * 36]);
#pragma unroll
        for (int w = 0; w < 9; w++) z8[w] = 0ull;
    }

#pragma unroll
    for (int j = 0; j < 4; j++) {
        float x = xs[j];
        __half* dst = &sv[t * 36 + j * 9];
        dst[8] = __float2half_rn(x);
        float s = (x + 0.44f) * 12.5f;        // (x - t0)/h
        int m = (int)floorf(s);
        if (m >= 0 && m <= 10) {
            float u  = s - (float)m;
            float v  = 1.0f - u;
            float u2 = u * u, u3 = u2 * u;
            const float c6 = 1.0f / 6.0f;
            float nv0 = v * v * v * c6;
            float nv1 = (3.0f * u3 - 6.0f * u2 + 4.0f) * c6;
            float nv2 = (-3.0f * u3 + 3.0f * u2 + 3.0f * u + 1.0f) * c6;
            float nv3 = u3 * c6;
            int j0 = m - 3;
            if (j0 >= 0 && j0 < 8)         dst[j0]     = __float2half_rn(nv0);
            if (j0 + 1 >= 0 && j0 + 1 < 8) dst[j0 + 1] = __float2half_rn(nv1);
            if (j0 + 2 >= 0 && j0 + 2 < 8) dst[j0 + 2] = __float2half_rn(nv2);
            if (j0 + 3 >= 0 && j0 + 3 < 8) dst[j0 + 3] = __float2half_rn(nv3);
        }
    }
    __syncthreads();

    const float4* s4 = reinterpret_cast<const float4*>(sv);
    float4* d4 = reinterpret_cast<float4*>(&g_F[(size_t)n * KTOT]);
#pragma unroll
    for (int c = t; c < 1152; c += 256) d4[c] = s4[c];
}

// ---------------------------------------------------------------------------
// GEMM: C = F * W^T, fp16 HMMA, fp32 accum. CTA 128x128x64, 8 warps (2m x 4n),
// 3-stage cp.async, SW128, one barrier per k-tile.
// ---------------------------------------------------------------------------
__device__ __forceinline__ void load_stage(
    uint32_t sbuf, int kt, int m0, int n0, int tid,
    const __half* __restrict__ A, const __half* __restrict__ B) {
#pragma unroll
    for (int j = 0; j < 4; j++) {
        int c = tid + j * 256;
        uint32_t row = (uint32_t)c >> 3, ch = (uint32_t)c & 7;
        uint32_t soff = sw128(row, ch);
        size_t gA = (size_t)(m0 + row) * KTOT + kt * BK + ch * 8;
        size_t gB = (size_t)(n0 + row) * KTOT + kt * BK + ch * 8;
        cp16(sbuf + soff,          A + gA);
        cp16(sbuf + APLANE + soff, B + gB);
    }
}

__global__ __launch_bounds__(256, 2) void kan_gemm_kernel(int layer,
                                                          float* __restrict__ Cout) {
    extern __shared__ char smem[];
    uint32_t sb;
    {
        uint64_t tmp;
        asm("cvta.to.shared.u64 %0, %1;" : "=l"(tmp) : "l"(smem));
        sb = (uint32_t)tmp;
    }
    const __half* __restrict__ A = g_F;
    const __half* __restrict__ B = layer ? g_W2 : g_W1;
    float* __restrict__ C = layer ? Cout : g_X1;

    const int tid = threadIdx.x;
    const int lane = tid & 31;
    const int wid = tid >> 5;
    const int warp_m = wid & 1;        // 2 m-slots of 64
    const int warp_n = wid >> 1;       // 4 n-slots of 32
    const int m0 = blockIdx.y * BM;
    const int n0 = blockIdx.x * BN;

    float acc[4][4][4];
#pragma unroll
    for (int i = 0; i < 4; i++)
#pragma unroll
        for (int j = 0; j < 4; j++)
#pragma unroll
            for (int r = 0; r < 4; r++) acc[i][j][r] = 0.0f;

    // prologue: stages 0 and 1 (2 committed groups -> loop uses cp_wait<1>)
    load_stage(sb, 0, m0, n0, tid, A, B);
    cp_commit();
    load_stage(sb + STAGE, 1, m0, n0, tid, A, B);
    cp_commit();

    // per-lane ldmatrix row/chunk bases
    const uint32_t arow = warp_m * 64 + (lane & 15);          // + mf*16
    const uint32_t achk = (uint32_t)(lane >> 4);              // + ks*2
    const uint32_t brow = warp_n * 32 + ((lane >> 4) << 3) + (lane & 7); // + nfp*16
    const uint32_t bchk = (uint32_t)((lane >> 3) & 1);        // + ks*2

    for (int kt = 0; kt < NKT; kt += 3) {
#pragma unroll
        for (int s = 0; s < 3; s++) {
            const int k = kt + s;
            // pending = {k, k+1}; wait until <=1 -> stage k landed
            cp_wait<1>();
            __syncthreads();   // publish stage k; fences iter k-1 reads of
                               // buffer (k+2)%3

            const uint32_t pbuf = sb + ((s + 2) % 3) * STAGE;
            const int u = k + 2;
            if (u < NKT)
                load_stage(pbuf, u, m0, n0, tid, A, B);
            cp_commit();

            const uint32_t buf = sb + s * STAGE;
#pragma unroll
            for (int ks = 0; ks < 4; ks++) {
                uint32_t af[4][4], bf[4][2];
#pragma unroll
                for (int mf = 0; mf < 4; mf++)
                    ldsm4(af[mf], buf + sw128(arow + mf * 16, achk + ks * 2));
#pragma unroll
                for (int nfp = 0; nfp < 2; nfp++) {
                    uint32_t rb = buf + APLANE +
                                  sw128(brow + nfp * 16, bchk + ks * 2);
                    uint32_t r4[4];
                    ldsm4(r4, rb);
                    bf[nfp * 2][0] = r4[0]; bf[nfp * 2][1] = r4[1];
                    bf[nfp * 2 + 1][0] = r4[2]; bf[nfp * 2 + 1][1] = r4[3];
                }
#pragma unroll
                for (int mf = 0; mf < 4; mf++)
#pragma unroll
                    for (int nf = 0; nf < 4; nf++)
                        mma16816(acc[mf][nf], af[mf], bf[nf]);
            }
        }
    }

    // epilogue: fp32 out (g_X1 for layer 0, harness out for layer 1)
#pragma unroll
    for (int mf = 0; mf < 4; mf++) {
        int row = m0 + warp_m * 64 + mf * 16 + (lane >> 2);
#pragma unroll
        for (int nf = 0; nf < 4; nf++) {
            int col = n0 + warp_n * 32 + nf * 8 + (lane & 3) * 2;
            float2* p0 = reinterpret_cast<float2*>(&C[(size_t)row * CH + col]);
            float2* p1 = reinterpret_cast<float2*>(&C[(size_t)(row + 8) * CH + col]);
            *p0 = make_float2(acc[mf][nf][0], acc[mf][nf][1]);
            *p1 = make_float2(acc[mf][nf][2], acc[mf][nf][3]);
        }
    }
}

// ---------------------------------------------------------------------------
// Launch: pack -> basis1 -> gemm1 -> basis2 -> gemm2
// ---------------------------------------------------------------------------
extern "C" void kernel_launch(void* const* d_in, const int* in_sizes, int n_in,
                              void* d_out, int out_size) {
    (void)in_sizes; (void)n_in; (void)out_size;
    const float* x   = (const float*)d_in[0];
    const float* bw1 = (const float*)d_in[1];
    const float* sw1 = (const float*)d_in[2];
    const float* bw2 = (const float*)d_in[3];
    const float* sw2 = (const float*)d_in[4];
    float* out = (float*)d_out;

    cudaFuncSetAttribute(kan_gemm_kernel,
                         cudaFuncAttributeMaxDynamicSharedMemorySize, SMEM_TOTAL);

    dim3 packGrid(CH, 2);
    pack_w_kernel<<<packGrid, 256>>>(bw1, sw1, bw2, sw2);

    dim3 gemmGrid(CH / BN, N_TOK / BM);   // (8, 64)

    basis_kernel<<<N_TOK, 256>>>(x, 0);
    kan_gemm_kernel<<<gemmGrid, 256, SMEM_TOTAL>>>(0, out);
    basis_kernel<<<N_TOK, 256>>>(x, 1);
    kan_gemm_kernel<<<gemmGrid, 256, SMEM_TOTAL>>>(1, out);
}

// round 14
// speedup vs baseline: 1.2090x; 1.0014x over previous
#include <cuda_runtime.h>
#include <cuda_fp16.h>
#include <cstdint>

// ---------------------------------------------------------------------------
// Problem constants
// ---------------------------------------------------------------------------
#define N_TOK 8192
#define CH    1024
#define KC    9
#define KTOT  (CH * KC)          // 9216

// GEMM tiling
#define BM 128
#define BN 128
#define BK 64
#define NKT (KTOT / BK)          // 144 k-tiles (divisible by 3)
#define APLANE 16384             // 128 rows x 128B (SW128 swizzled)
#define STAGE (2 * APLANE)       // A, B = 32 KB
#define SMEM_TOTAL 98304         // 3 stages = 96 KB -> 2 CTAs/SM

// ---------------------------------------------------------------------------
// Device scratch
// ---------------------------------------------------------------------------
__device__ __align__(16) __half g_F  [(size_t)N_TOK * KTOT];
__device__ __align__(16) __half g_W1 [(size_t)CH * KTOT];
__device__ __align__(16) __half g_W2 [(size_t)CH * KTOT];
__device__ __align__(16) float  g_X1 [(size_t)N_TOK * CH];

// ---------------------------------------------------------------------------
// PTX helpers (sm_80-baseline only)
// ---------------------------------------------------------------------------
__device__ __forceinline__ void cp16(uint32_t s, const void* g) {
    asm volatile("cp.async.cg.shared.global [%0], [%1], 16;" :: "r"(s), "l"(g));
}
__device__ __forceinline__ void cp_commit() {
    asm volatile("cp.async.commit_group;" ::: "memory");
}
template <int N> __device__ __forceinline__ void cp_wait() {
    asm volatile("cp.async.wait_group %0;" :: "n"(N) : "memory");
}
__device__ __forceinline__ void ldsm4(uint32_t* r, uint32_t a) {
    asm volatile("ldmatrix.sync.aligned.m8n8.x4.shared.b16 {%0,%1,%2,%3}, [%4];"
                 : "=r"(r[0]), "=r"(r[1]), "=r"(r[2]), "=r"(r[3]) : "r"(a));
}
__device__ __forceinline__ void mma16816(float* c, const uint32_t* a,
                                         const uint32_t* b) {
    asm volatile(
        "mma.sync.aligned.m16n8k16.row.col.f32.f16.f16.f32 "
        "{%0,%1,%2,%3}, {%4,%5,%6,%7}, {%8,%9}, {%0,%1,%2,%3};"
        : "+f"(c[0]), "+f"(c[1]), "+f"(c[2]), "+f"(c[3])
        : "r"(a[0]), "r"(a[1]), "r"(a[2]), "r"(a[3]), "r"(b[0]), "r"(b[1]));
}
// SW128 swizzle within a 16KB plane: row in [0,128), chunk in [0,8) (16B units)
__device__ __forceinline__ uint32_t sw128(uint32_t row, uint32_t chunk) {
    return row * 128u + ((chunk ^ (row & 7u)) << 4);
}

// ---------------------------------------------------------------------------
// Prep kernel: blocks [0, N_TOK) = basis-1 rows; blocks [N_TOK, N_TOK+2*CH)
// = weight-pack rows. Bodies identical to the R12 proven kernels.
// ---------------------------------------------------------------------------
__global__ __launch_bounds__(256) void prep_kernel(
    const float* __restrict__ x,
    const float* __restrict__ base_w1, const float* __restrict__ spline_w1,
    const float* __restrict__ base_w2, const float* __restrict__ spline_w2) {
    __shared__ __align__(16) __half sv[KTOT];   // 18432 B
    int b = blockIdx.x;
    int t = threadIdx.x;

    if (b < N_TOK) {
        // ---- basis-1 row b ----
        int n = b;
        float4 x4 = reinterpret_cast<const float4*>(x + (size_t)n * CH)[t];
        float xs[4] = {x4.x, x4.y, x4.z, x4.w};
        {
            uint64_t* z8 = reinterpret_cast<uint64_t*>(&sv[t * 36]);
#pragma unroll
            for (int w = 0; w < 9; w++) z8[w] = 0ull;
        }
#pragma unroll
        for (int j = 0; j < 4; j++) {
            float xv = xs[j];
            __half* dst = &sv[t * 36 + j * 9];
            dst[8] = __float2half_rn(xv);
            float s = (xv + 0.44f) * 12.5f;
            int m = (int)floorf(s);
            if (m >= 0 && m <= 10) {
                float u  = s - (float)m;
                float v  = 1.0f - u;
                float u2 = u * u, u3 = u2 * u;
                const float c6 = 1.0f / 6.0f;
                float nv0 = v * v * v * c6;
                float nv1 = (3.0f * u3 - 6.0f * u2 + 4.0f) * c6;
                float nv2 = (-3.0f * u3 + 3.0f * u2 + 3.0f * u + 1.0f) * c6;
                float nv3 = u3 * c6;
                int j0 = m - 3;
                if (j0 >= 0 && j0 < 8)         dst[j0]     = __float2half_rn(nv0);
                if (j0 + 1 >= 0 && j0 + 1 < 8) dst[j0 + 1] = __float2half_rn(nv1);
                if (j0 + 2 >= 0 && j0 + 2 < 8) dst[j0 + 2] = __float2half_rn(nv2);
                if (j0 + 3 >= 0 && j0 + 3 < 8) dst[j0 + 3] = __float2half_rn(nv3);
            }
        }
        __syncthreads();
        const float4* s4 = reinterpret_cast<const float4*>(sv);
        float4* d4 = reinterpret_cast<float4*>(&g_F[(size_t)n * KTOT]);
#pragma unroll
        for (int c = t; c < 1152; c += 256) d4[c] = s4[c];
    } else {
        // ---- weight pack ----
        int r = b - N_TOK;
        int which = r >> 10;              // / CH
        int n = r & (CH - 1);
        const float* __restrict__ bw = which ? base_w2 : base_w1;
        const float* __restrict__ sp = which ? spline_w2 : spline_w1;
        __half* __restrict__ W = which ? g_W2 : g_W1;
#pragma unroll
        for (int j = 0; j < 4; j++) {
            int i = t + j * 256;
            const float4* s4 = reinterpret_cast<const float4*>(
                sp + ((size_t)n * CH + i) * 8);
            float4 a = s4[0], bb = s4[1];
            float base = bw[(size_t)n * CH + i];
            __half* dst = &sv[i * 9];
            dst[0] = __float2half_rn(a.x);  dst[1] = __float2half_rn(a.y);
            dst[2] = __float2half_rn(a.z);  dst[3] = __float2half_rn(a.w);
            dst[4] = __float2half_rn(bb.x); dst[5] = __float2half_rn(bb.y);
            dst[6] = __float2half_rn(bb.z); dst[7] = __float2half_rn(bb.w);
            dst[8] = __float2half_rn(base);
        }
        __syncthreads();
        const float4* s4 = reinterpret_cast<const float4*>(sv);
        float4* d4 = reinterpret_cast<float4*>(W + (size_t)n * KTOT);
#pragma unroll
        for (int c = t; c < 1152; c += 256) d4[c] = s4[c];
    }
}

// ---------------------------------------------------------------------------
// Basis-2: one token row per block (reads g_X1), identical body to R12.
// ---------------------------------------------------------------------------
__global__ __launch_bounds__(256) void basis_kernel() {
    const float* __restrict__ X = g_X1;
    __shared__ __align__(16) __half sv[KTOT];

    int n = blockIdx.x;
    int t = threadIdx.x;
    float4 x4 = reinterpret_cast<const float4*>(X + (size_t)n * CH)[t];
    float xs[4] = {x4.x, x4.y, x4.z, x4.w};

    {
        uint64_t* z8 = reinterpret_cast<uint64_t*>(&sv[t * 36]);
#pragma unroll
        for (int w = 0; w < 9; w++) z8[w] = 0ull;
    }
#pragma unroll
    for (int j = 0; j < 4; j++) {
        float x = xs[j];
        __half* dst = &sv[t * 36 + j * 9];
        dst[8] = __float2half_rn(x);
        float s = (x + 0.44f) * 12.5f;
        int m = (int)floorf(s);
        if (m >= 0 && m <= 10) {
            float u  = s - (float)m;
            float v  = 1.0f - u;
            float u2 = u * u, u3 = u2 * u;
            const float c6 = 1.0f / 6.0f;
            float nv0 = v * v * v * c6;
            float nv1 = (3.0f * u3 - 6.0f * u2 + 4.0f) * c6;
            float nv2 = (-3.0f * u3 + 3.0f * u2 + 3.0f * u + 1.0f) * c6;
            float nv3 = u3 * c6;
            int j0 = m - 3;
            if (j0 >= 0 && j0 < 8)         dst[j0]     = __float2half_rn(nv0);
            if (j0 + 1 >= 0 && j0 + 1 < 8) dst[j0 + 1] = __float2half_rn(nv1);
            if (j0 + 2 >= 0 && j0 + 2 < 8) dst[j0 + 2] = __float2half_rn(nv2);
            if (j0 + 3 >= 0 && j0 + 3 < 8) dst[j0 + 3] = __float2half_rn(nv3);
        }
    }
    __syncthreads();

    const float4* s4 = reinterpret_cast<const float4*>(sv);
    float4* d4 = reinterpret_cast<float4*>(&g_F[(size_t)n * KTOT]);
#pragma unroll
    for (int c = t; c < 1152; c += 256) d4[c] = s4[c];
}

// ---------------------------------------------------------------------------
// GEMM: byte-identical mainloop to R12 (proven): prefetch BEFORE the ks loop.
// CTA 128x128x64, 8 warps (2m x 4n), 3-stage cp.async, SW128.
// ---------------------------------------------------------------------------
__device__ __forceinline__ void load_stage(
    uint32_t sbuf, int kt, int m0, int n0, int tid,
    const __half* __restrict__ A, const __half* __restrict__ B) {
#pragma unroll
    for (int j = 0; j < 4; j++) {
        int c = tid + j * 256;
        uint32_t row = (uint32_t)c >> 3, ch = (uint32_t)c & 7;
        uint32_t soff = sw128(row, ch);
        size_t gA = (size_t)(m0 + row) * KTOT + kt * BK + ch * 8;
        size_t gB = (size_t)(n0 + row) * KTOT + kt * BK + ch * 8;
        cp16(sbuf + soff,          A + gA);
        cp16(sbuf + APLANE + soff, B + gB);
    }
}

__global__ __launch_bounds__(256, 2) void kan_gemm_kernel(int layer,
                                                          float* __restrict__ Cout) {
    extern __shared__ char smem[];
    uint32_t sb;
    {
        uint64_t tmp;
        asm("cvta.to.shared.u64 %0, %1;" : "=l"(tmp) : "l"(smem));
        sb = (uint32_t)tmp;
    }
    const __half* __restrict__ A = g_F;
    const __half* __restrict__ B = layer ? g_W2 : g_W1;
    float* __restrict__ C = layer ? Cout : g_X1;

    const int tid = threadIdx.x;
    const int lane = tid & 31;
    const int wid = tid >> 5;
    const int warp_m = wid & 1;
    const int warp_n = wid >> 1;
    const int m0 = blockIdx.y * BM;
    const int n0 = blockIdx.x * BN;

    float acc[4][4][4];
#pragma unroll
    for (int i = 0; i < 4; i++)
#pragma unroll
        for (int j = 0; j < 4; j++)
#pragma unroll
            for (int r = 0; r < 4; r++) acc[i][j][r] = 0.0f;

    // prologue: stages 0 and 1 (2 committed groups -> loop uses cp_wait<1>)
    load_stage(sb, 0, m0, n0, tid, A, B);
    cp_commit();
    load_stage(sb + STAGE, 1, m0, n0, tid, A, B);
    cp_commit();

    const uint32_t arow = warp_m * 64 + (lane & 15);
    const uint32_t achk = (uint32_t)(lane >> 4);
    const uint32_t brow = warp_n * 32 + ((lane >> 4) << 3) + (lane & 7);
    const uint32_t bchk = (uint32_t)((lane >> 3) & 1);

    for (int kt = 0; kt < NKT; kt += 3) {
#pragma unroll
        for (int s = 0; s < 3; s++) {
            const int k = kt + s;
            // pending = {k, k+1}; wait until <=1 -> stage k landed
            cp_wait<1>();
            __syncthreads();   // publish stage k; fences iter k-1 reads of
                               // buffer (k+2)%3

            const uint32_t pbuf = sb + ((s + 2) % 3) * STAGE;
            const int u = k + 2;
            if (u < NKT)
                load_stage(pbuf, u, m0, n0, tid, A, B);
            cp_commit();

            const uint32_t buf = sb + s * STAGE;
#pragma unroll
            for (int ks = 0; ks < 4; ks++) {
                uint32_t af[4][4], bf[4][2];
#pragma unroll
                for (int mf = 0; mf < 4; mf++)
                    ldsm4(af[mf], buf + sw128(arow + mf * 16, achk + ks * 2));
#pragma unroll
                for (int nfp = 0; nfp < 2; nfp++) {
                    uint32_t rb = buf + APLANE +
                                  sw128(brow + nfp * 16, bchk + ks * 2);
                    uint32_t r4[4];
                    ldsm4(r4, rb);
                    bf[nfp * 2][0] = r4[0]; bf[nfp * 2][1] = r4[1];
                    bf[nfp * 2 + 1][0] = r4[2]; bf[nfp * 2 + 1][1] = r4[3];
                }
#pragma unroll
                for (int mf = 0; mf < 4; mf++)
#pragma unroll
                    for (int nf = 0; nf < 4; nf++)
                        mma16816(acc[mf][nf], af[mf], bf[nf]);
            }
        }
    }

    // epilogue: fp32 out (g_X1 for layer 0, harness out for layer 1)
#pragma unroll
    for (int mf = 0; mf < 4; mf++) {
        int row = m0 + warp_m * 64 + mf * 16 + (lane >> 2);
#pragma unroll
        for (int nf = 0; nf < 4; nf++) {
            int col = n0 + warp_n * 32 + nf * 8 + (lane & 3) * 2;
            float2* p0 = reinterpret_cast<float2*>(&C[(size_t)row * CH + col]);
            float2* p1 = reinterpret_cast<float2*>(&C[(size_t)(row + 8) * CH + col]);
            *p0 = make_float2(acc[mf][nf][0], acc[mf][nf][1]);
            *p1 = make_float2(acc[mf][nf][2], acc[mf][nf][3]);
        }
    }
}

// ---------------------------------------------------------------------------
// Launch: prep (basis1 + pack) -> gemm1 -> basis2 -> gemm2
// ---------------------------------------------------------------------------
extern "C" void kernel_launch(void* const* d_in, const int* in_sizes, int n_in,
                              void* d_out, int out_size) {
    (void)in_sizes; (void)n_in; (void)out_size;
    const float* x   = (const float*)d_in[0];
    const float* bw1 = (const float*)d_in[1];
    const float* sw1 = (const float*)d_in[2];
    const float* bw2 = (const float*)d_in[3];
    const float* sw2 = (const float*)d_in[4];
    float* out = (float*)d_out;

    cudaFuncSetAttribute(kan_gemm_kernel,
                         cudaFuncAttributeMaxDynamicSharedMemorySize, SMEM_TOTAL);

    dim3 gemmGrid(CH / BN, N_TOK / BM);   // (8, 64)

    prep_kernel<<<N_TOK + 2 * CH, 256>>>(x, bw1, sw1, bw2, sw2);
    kan_gemm_kernel<<<gemmGrid, 256, SMEM_TOTAL>>>(0, out);
    basis_kernel<<<N_TOK, 256>>>();
    kan_gemm_kernel<<<gemmGrid, 256, SMEM_TOTAL>>>(1, out);
}